// round 15
// baseline (speedup 1.0000x reference)
#include <cuda_runtime.h>
#include <cuda_bf16.h>
#include <cstdint>

// ---------------- problem constants ----------------
#define NTOK   16384
#define HIN    768
#define NPACK  1536      // grouped gate cols: 16 groups x 96 (= i|g|o x 32 j)
#define HIDC   512
#define NTAG   20
#define NCHUNK 256
#define CLEN   64
#define NEGV   (-10000.0f)

// ---------------- device scratch ----------------
__device__ __nv_bfloat16 d_Ahi[(size_t)NTOK * HIN];
__device__ __nv_bfloat16 d_Alo[(size_t)NTOK * HIN];
__device__ __nv_bfloat16 d_Bhi[(size_t)NPACK * HIN];   // grouped rows, K-major
__device__ __nv_bfloat16 d_Blo[(size_t)NPACK * HIN];
__device__ float d_biasG[NPACK];
__device__ float d_enc[(size_t)NTOK * HIDC];
__device__ float d_feats[NTOK * NTAG];
__device__ float d_P[NCHUNK * NTAG * NTAG];
__device__ float d_fvs[NCHUNK * NTAG];
__device__ float d_finalfv[NTAG];
__device__ unsigned char d_bps[NTOK * NTAG];
__device__ unsigned char d_Wc[NCHUNK * NTAG];
__device__ unsigned char d_r[NCHUNK];

// ---------------- helpers ----------------
__device__ __forceinline__ uint32_t smem_u32(const void* p) {
    uint32_t a;
    asm("{ .reg .u64 t; cvta.to.shared.u64 t, %1; cvt.u32.u64 %0, t; }" : "=r"(a) : "l"(p));
    return a;
}
#define CP_ASYNC16(dst, src) \
    asm volatile("cp.async.cg.shared.global [%0], [%1], 16;" :: "r"(dst), "l"(src))
#define CP_COMMIT() asm volatile("cp.async.commit_group;" ::: "memory")
#define CP_WAIT(n)  asm volatile("cp.async.wait_group %0;" :: "n"(n) : "memory")

__device__ __forceinline__ void ldm_x4(uint32_t* r, uint32_t addr) {
    asm volatile("ldmatrix.sync.aligned.m8n8.x4.shared.b16 {%0,%1,%2,%3}, [%4];"
                 : "=r"(r[0]), "=r"(r[1]), "=r"(r[2]), "=r"(r[3]) : "r"(addr));
}
__device__ __forceinline__ void mma16816(float* c, const uint32_t* a, uint32_t b0, uint32_t b1) {
    asm volatile(
        "mma.sync.aligned.m16n8k16.row.col.f32.bf16.bf16.f32 "
        "{%0,%1,%2,%3}, {%4,%5,%6,%7}, {%8,%9}, {%0,%1,%2,%3};"
        : "+f"(c[0]), "+f"(c[1]), "+f"(c[2]), "+f"(c[3])
        : "r"(a[0]), "r"(a[1]), "r"(a[2]), "r"(a[3]), "r"(b0), "r"(b1));
}
__device__ __forceinline__ void split2(float f, __nv_bfloat16& h, __nv_bfloat16& l) {
    h = __float2bfloat16_rn(f);
    l = __float2bfloat16_rn(f - __bfloat162float(h));
}

// ---------------- K0: merged input split + weight pack ----------------
// grouped row n: g = n/96 (dir=g>>3, jblk=g&7), cg=n%96, gate=cg/32, jj=cg%32
#define XBLK ((NTOK * HIN / 4) / 256)     // 12288
#define WBLK ((NPACK * HIN / 4) / 256)    // 1152
__global__ void prep_kernel(const float* __restrict__ x,
                            const float* __restrict__ wf, const float* __restrict__ wb,
                            const float* __restrict__ bihf, const float* __restrict__ bhhf,
                            const float* __restrict__ bihb, const float* __restrict__ bhhb) {
    int b = blockIdx.x;
    if (b < XBLK) {
        int idx = b * 256 + threadIdx.x;
        float4 v = *(const float4*)(x + HIN + (size_t)idx * 4);  // skip token 0
        float f[4] = {v.x, v.y, v.z, v.w};
        __nv_bfloat16 hi[4], lo[4];
#pragma unroll
        for (int i = 0; i < 4; i++) split2(f[i], hi[i], lo[i]);
        *(ulonglong1*)(d_Ahi + (size_t)idx * 4) = *(ulonglong1*)hi;
        *(ulonglong1*)(d_Alo + (size_t)idx * 4) = *(ulonglong1*)lo;
    } else {
        int idx = (b - XBLK) * 256 + threadIdx.x;
        int n = idx / (HIN / 4);
        int kq = (idx % (HIN / 4)) * 4;
        int g = n / 96, cg = n % 96;
        int dir = g >> 3, jblk = g & 7;
        int gate = cg / 32, jj = cg % 32;
        int gateoff = (gate == 0) ? 0 : (gate == 1 ? 512 : 768);
        int r = gateoff + jblk * 32 + jj;
        const float* w = dir ? wb : wf;
        float4 v = *(const float4*)(w + (size_t)r * HIN + kq);
        float f[4] = {v.x, v.y, v.z, v.w};
        __nv_bfloat16 hi[4], lo[4];
#pragma unroll
        for (int i = 0; i < 4; i++) split2(f[i], hi[i], lo[i]);
        *(ulonglong1*)(d_Bhi + (size_t)n * HIN + kq) = *(ulonglong1*)hi;
        *(ulonglong1*)(d_Blo + (size_t)n * HIN + kq) = *(ulonglong1*)lo;
        if (kq == 0) {
            const float* bih = dir ? bihb : bihf;
            const float* bhh = dir ? bhhb : bhhf;
            d_biasG[n] = bih[r] + bhh[r];
        }
    }
}

// ---------------- K1: fused single-pass 3-product bf16 GEMM + LSTM activation ----------------
// CTA tile 128x96, 256 threads, 8 warps (warp tile 32x48), 2 CTAs/SM.
// Per 32-k stage: load Ahi,Alo (128x32 each) + Bhi,Blo (96x32 each) ONCE,
// issue AhiBhi + AhiBlo + AloBhi into the same f32 accumulators.
#define BKE 32
#define ASTR 40
#define NKI 24                    // 768/32
#define RA (128 * ASTR)           // one A region (elements)
#define RB (96 * ASTR)
#define SSTG (2 * RA + 2 * RB)    // 17920 elements = 35840 B per stage
#define OFF_AH 0
#define OFF_AL RA
#define OFF_BH (2 * RA)
#define OFF_BL (2 * RA + RB)
#define NST 3
#define GSMEM (NST * SSTG * 2)    // 107520 B
#define EXSTR 100

__global__ __launch_bounds__(256, 2) void gemm_fused() {
    extern __shared__ char dsm[];
    __nv_bfloat16* Ssm = (__nv_bfloat16*)dsm;
    float* Ex = (float*)dsm;                 // epilogue overlay: 64 x EXSTR fp32
    int tid = threadIdx.x;
    int wid = tid >> 5, lane = tid & 31;
    int wm = wid >> 1, wn = wid & 1;         // warp tile 32 x 48 (wm 0..3, wn 0..1)
    int g = blockIdx.x, bm = blockIdx.y;

    uint32_t sS = smem_u32(Ssm);
    const __nv_bfloat16* Agh = d_Ahi + (size_t)(bm * 128) * HIN;
    const __nv_bfloat16* Agl = d_Alo + (size_t)(bm * 128) * HIN;
    const __nv_bfloat16* Bgh = d_Bhi + (size_t)(g * 96) * HIN;
    const __nv_bfloat16* Bgl = d_Blo + (size_t)(g * 96) * HIN;

    float acc[2][6][4];
#pragma unroll
    for (int i = 0; i < 2; i++)
#pragma unroll
        for (int j = 0; j < 6; j++)
#pragma unroll
            for (int q = 0; q < 4; q++) acc[i][j][q] = 0.f;

#define LOAD_STAGE(s, kt)                                                                  \
    do {                                                                                   \
        uint32_t base_ = sS + (uint32_t)((s) * SSTG * 2);                                  \
        _Pragma("unroll")                                                                  \
        for (int i_ = 0; i_ < 2; i_++) {                                                   \
            int c_ = tid + i_ * 256;                                                       \
            int row_ = c_ >> 2, seg_ = c_ & 3;                                             \
            uint32_t so_ = (uint32_t)((row_ * ASTR + seg_ * 8) * 2);                       \
            size_t go_ = (size_t)row_ * HIN + (kt) * BKE + seg_ * 8;                       \
            CP_ASYNC16(base_ + OFF_AH * 2 + so_, Agh + go_);                               \
            CP_ASYNC16(base_ + OFF_AL * 2 + so_, Agl + go_);                               \
        }                                                                                  \
        _Pragma("unroll")                                                                  \
        for (int i_ = 0; i_ < 2; i_++) {                                                   \
            int c_ = tid + i_ * 256;                                                       \
            if (c_ < 384) {                                                                \
                int row_ = c_ >> 2, seg_ = c_ & 3;                                         \
                uint32_t so_ = (uint32_t)((row_ * ASTR + seg_ * 8) * 2);                   \
                size_t go_ = (size_t)row_ * HIN + (kt) * BKE + seg_ * 8;                   \
                CP_ASYNC16(base_ + OFF_BH * 2 + so_, Bgh + go_);                           \
                CP_ASYNC16(base_ + OFF_BL * 2 + so_, Bgl + go_);                           \
            }                                                                              \
        }                                                                                  \
    } while (0)

    LOAD_STAGE(0, 0); CP_COMMIT();
    LOAD_STAGE(1, 1); CP_COMMIT();

    for (int kt = 0; kt < NKI; kt++) {
        if (kt < NKI - 1) { CP_WAIT(1); }
        else { CP_WAIT(0); }
        __syncthreads();
        int cs = kt % NST;
        uint32_t sbase = sS + (uint32_t)(cs * SSTG * 2);

#pragma unroll
        for (int ks = 0; ks < 2; ks++) {
            int k0 = ks * 16;
            int arow = wm * 32 + (lane & 15);
            int hl = (lane >> 4) * 8;
            uint32_t afh[2][4], afl[2][4];
#pragma unroll
            for (int i = 0; i < 2; i++) {
                uint32_t ro = (uint32_t)(((arow + i * 16) * ASTR + k0 + hl) * 2);
                ldm_x4(afh[i], sbase + OFF_AH * 2 + ro);
                ldm_x4(afl[i], sbase + OFF_AL * 2 + ro);
            }
            uint32_t bfh[3][4], bfl[3][4];
#pragma unroll
            for (int p = 0; p < 3; p++) {
                int brow = wn * 48 + p * 16 + (lane & 15);
                uint32_t ro = (uint32_t)((brow * ASTR + k0 + hl) * 2);
                ldm_x4(bfh[p], sbase + OFF_BH * 2 + ro);
                ldm_x4(bfl[p], sbase + OFF_BL * 2 + ro);
            }
#pragma unroll
            for (int i = 0; i < 2; i++)
#pragma unroll
                for (int p = 0; p < 3; p++) {
                    mma16816(acc[i][2 * p + 0], afh[i], bfh[p][0], bfh[p][2]);
                    mma16816(acc[i][2 * p + 1], afh[i], bfh[p][1], bfh[p][3]);
                    mma16816(acc[i][2 * p + 0], afh[i], bfl[p][0], bfl[p][2]);
                    mma16816(acc[i][2 * p + 1], afh[i], bfl[p][1], bfl[p][3]);
                    mma16816(acc[i][2 * p + 0], afl[i], bfh[p][0], bfh[p][2]);
                    mma16816(acc[i][2 * p + 1], afl[i], bfh[p][1], bfh[p][3]);
                }
        }

        if (kt + 2 < NKI) {
            LOAD_STAGE((kt + 2) % NST, kt + 2);
            CP_COMMIT();
        }
    }
    __syncthreads();

    // ---- fused epilogue: bias + LSTM activation -> enc ----
    float2 bias[6];
#pragma unroll
    for (int jt = 0; jt < 6; jt++) {
        int col = g * 96 + wn * 48 + jt * 8 + (lane & 3) * 2;
        bias[jt] = *(const float2*)(d_biasG + col);
    }
    int dir = g >> 3, jblk = g & 7;
    int base = dir * 256 + jblk * 32;

#pragma unroll
    for (int ch = 0; ch < 2; ch++) {
        if ((wm >> 1) == ch) {
#pragma unroll
            for (int i = 0; i < 2; i++) {
                int r = (wm & 1) * 32 + i * 16 + (lane >> 2);
                int cbase = wn * 48 + (lane & 3) * 2;
#pragma unroll
                for (int jt = 0; jt < 6; jt++) {
                    int c = cbase + jt * 8;
                    Ex[r * EXSTR + c]           = acc[i][jt][0] + bias[jt].x;
                    Ex[r * EXSTR + c + 1]       = acc[i][jt][1] + bias[jt].y;
                    Ex[(r + 8) * EXSTR + c]     = acc[i][jt][2] + bias[jt].x;
                    Ex[(r + 8) * EXSTR + c + 1] = acc[i][jt][3] + bias[jt].y;
                }
            }
        }
        __syncthreads();
        // 64 rows x 32 j outputs = 2048 -> 8 iters of 256 threads
#pragma unroll
        for (int u = 0; u < 8; u++) {
            int idx = u * 256 + tid;
            int r = idx >> 5, j = idx & 31;
            float iv = Ex[r * EXSTR + j];
            float gv = Ex[r * EXSTR + 32 + j];
            float ov = Ex[r * EXSTR + 64 + j];
            float si = 1.f / (1.f + expf(-iv));
            float cc = si * tanhf(gv);
            float so = 1.f / (1.f + expf(-ov));
            d_enc[(size_t)(bm * 128 + ch * 64 + r) * HIDC + base + j] = so * tanhf(cc);
        }
        __syncthreads();
    }
}

// ---------------- K3: feats = enc @ w_tag^T + b_tag ----------------
#define FT_TOK 32
__global__ __launch_bounds__(256) void feats_kernel(const float* __restrict__ wtag,
                                                    const float* __restrict__ btag) {
    extern __shared__ float esm[];   // [FT_TOK][HIDC] = 64KB
    int warp = threadIdx.x >> 5, lane = threadIdx.x & 31;
    int tw = warp & 3, half = warp >> 2;
    float wreg[5][16];
#pragma unroll
    for (int t = 0; t < 5; t++)
#pragma unroll
        for (int q = 0; q < 16; q++)
            wreg[t][q] = wtag[(tw * 5 + t) * HIDC + q * 32 + lane];
    float bloc[5];
#pragma unroll
    for (int t = 0; t < 5; t++) bloc[t] = btag[tw * 5 + t];

    int tok0 = blockIdx.x * FT_TOK;
    const float4* src = (const float4*)(d_enc + (size_t)tok0 * HIDC);
    float4* dst = (float4*)esm;
    for (int i = threadIdx.x; i < FT_TOK * HIDC / 4; i += 256) dst[i] = src[i];
    __syncthreads();

    for (int tk = 0; tk < 8; tk++) {
        int tokA = half * 16 + tk;
        int tokB = tokA + 8;
        float sA[5] = {0.f, 0.f, 0.f, 0.f, 0.f};
        float sB[5] = {0.f, 0.f, 0.f, 0.f, 0.f};
#pragma unroll
        for (int q = 0; q < 16; q++) {
            float eA = esm[tokA * HIDC + q * 32 + lane];
            float eB = esm[tokB * HIDC + q * 32 + lane];
#pragma unroll
            for (int t = 0; t < 5; t++) {
                sA[t] += eA * wreg[t][q];
                sB[t] += eB * wreg[t][q];
            }
        }
#pragma unroll
        for (int t = 0; t < 5; t++) {
#pragma unroll
            for (int off = 16; off > 0; off >>= 1) {
                sA[t] += __shfl_xor_sync(0xffffffffu, sA[t], off);
                sB[t] += __shfl_xor_sync(0xffffffffu, sB[t], off);
            }
        }
        if (lane == 0) {
#pragma unroll
            for (int t = 0; t < 5; t++) {
                d_feats[(tok0 + tokA) * NTAG + tw * 5 + t] = sA[t] + bloc[t];
                d_feats[(tok0 + tokB) * NTAG + tw * 5 + t] = sB[t] + bloc[t];
            }
        }
    }
}

// ---------------- V1: per-chunk maxplus products (tree max) ----------------
__global__ __launch_bounds__(512) void viterbi_chunk_prod(const float* __restrict__ trans) {
    __shared__ float fsm[CLEN * NTAG];
    __shared__ float P[2][NTAG][NTAG];
    int c = blockIdx.x, tid = threadIdx.x;
    for (int i = tid; i < CLEN * NTAG; i += 512) fsm[i] = d_feats[c * CLEN * NTAG + i];
    __syncthreads();
    int j = tid / NTAG, k = tid % NTAG;
    bool act = (tid < NTAG * NTAG);
    float tr[NTAG];
    if (act) {
#pragma unroll
        for (int m = 0; m < NTAG; m++) tr[m] = trans[j * NTAG + m];
        P[0][j][k] = trans[j * NTAG + k] + fsm[j];
    }
    __syncthreads();
    int buf = 0;
    for (int t = 1; t < CLEN; t++) {
        if (act) {
            float v0 = -1e30f, v1 = -1e30f, v2 = -1e30f, v3 = -1e30f;
#pragma unroll
            for (int mm = 0; mm < 5; mm++) {
                v0 = fmaxf(v0, tr[4 * mm + 0] + P[buf][4 * mm + 0][k]);
                v1 = fmaxf(v1, tr[4 * mm + 1] + P[buf][4 * mm + 1][k]);
                v2 = fmaxf(v2, tr[4 * mm + 2] + P[buf][4 * mm + 2][k]);
                v3 = fmaxf(v3, tr[4 * mm + 3] + P[buf][4 * mm + 3][k]);
            }
            float v = fmaxf(fmaxf(v0, v1), fmaxf(v2, v3));
            P[buf ^ 1][j][k] = v + fsm[t * NTAG + j];
        }
        buf ^= 1;
        __syncthreads();
    }
    if (act) d_P[c * NTAG * NTAG + j * NTAG + k] = P[buf][j][k];
}

// ---------------- V2: sequential scan with prefetch ----------------
__global__ void viterbi_scan() {
    __shared__ float Ps[NTAG * NTAG];
    __shared__ float fvsm[NTAG];
    int lane = threadIdx.x;
    float cur[13], nx[13];
#pragma unroll
    for (int t = 0; t < 13; t++) {
        int i = lane + 32 * t;
        cur[t] = (i < NTAG * NTAG) ? d_P[i] : 0.f;
    }
    float fv = (lane == 18) ? 0.f : NEGV;
    for (int c = 0; c < NCHUNK; c++) {
#pragma unroll
        for (int t = 0; t < 13; t++) {
            int i = lane + 32 * t;
            if (i < NTAG * NTAG) Ps[i] = cur[t];
        }
        if (lane < NTAG) { d_fvs[c * NTAG + lane] = fv; fvsm[lane] = fv; }
        __syncwarp();
        if (c + 1 < NCHUNK) {
#pragma unroll
            for (int t = 0; t < 13; t++) {
                int i = lane + 32 * t;
                nx[t] = (i < NTAG * NTAG) ? d_P[(c + 1) * NTAG * NTAG + i] : 0.f;
            }
        }
        if (lane < NTAG) {
            float nf = -1e30f;
#pragma unroll
            for (int k = 0; k < NTAG; k++) nf = fmaxf(nf, Ps[lane * NTAG + k] + fvsm[k]);
            fv = nf;
        }
        __syncwarp();
#pragma unroll
        for (int t = 0; t < 13; t++) cur[t] = nx[t];
    }
}

// ---------------- V3: per-chunk forward + backpointers + chunk table (merged) ----------------
__global__ void viterbi_forward(const float* __restrict__ trans) {
    __shared__ float fsm[CLEN * NTAG];
    __shared__ unsigned char bsm[CLEN * NTAG];
    int c = blockIdx.x, lane = threadIdx.x;
    for (int i = lane; i < CLEN * NTAG; i += 32) fsm[i] = d_feats[c * CLEN * NTAG + i];
    __syncwarp();
    bool act = lane < NTAG;
    float tr[NTAG];
    if (act) {
#pragma unroll
        for (int m = 0; m < NTAG; m++) tr[m] = trans[lane * NTAG + m];
    }
    float fv = act ? d_fvs[c * NTAG + lane] : -1e30f;
    for (int t = 0; t < CLEN; t++) {
        float best = -1e30f;
        int bi = 0;
#pragma unroll
        for (int k = 0; k < NTAG; k++) {
            float v = __shfl_sync(0xffffffffu, fv, k);
            if (act) {
                v += tr[k];
                if (v > best) { best = v; bi = k; }
            }
        }
        if (act) {
            bsm[t * NTAG + lane] = (unsigned char)bi;
            fv = best + fsm[t * NTAG + lane];
        }
    }
    if (c == NCHUNK - 1 && act) d_finalfv[lane] = fv;
    __syncwarp();
    uint4* dst = (uint4*)(d_bps + c * CLEN * NTAG);
    const uint4* srcv = (const uint4*)bsm;
    for (int i = lane; i < (CLEN * NTAG) / 16; i += 32) dst[i] = srcv[i];
    if (act) {
        int x = lane;
        for (int t = CLEN - 1; t >= 0; t--) x = bsm[t * NTAG + x];
        d_Wc[c * NTAG + lane] = (unsigned char)x;
    }
}

// ---------------- B2: terminal argmax + boundary scan ----------------
__global__ void terminal_and_scan(const float* __restrict__ trans, float* __restrict__ out) {
    __shared__ unsigned char Wsm[NCHUNK * NTAG];
    int lane = threadIdx.x;
    const uint4* src = (const uint4*)d_Wc;
    for (int i = lane; i < (NCHUNK * NTAG) / 16; i += 32) ((uint4*)Wsm)[i] = src[i];
    float term = (lane < NTAG) ? d_finalfv[lane] + trans[19 * NTAG + lane] : -1e30f;
    __syncwarp();
    float best = -1e30f;
    int bi = 0;
#pragma unroll
    for (int k = 0; k < NTAG; k++) {
        float v = __shfl_sync(0xffffffffu, term, k);
        if (v > best) { best = v; bi = k; }
    }
    if (lane == 0) {
        out[0] = best;
        int r = bi;
        d_r[NCHUNK - 1] = (unsigned char)r;
        for (int c = NCHUNK - 1; c >= 1; c--) {
            r = Wsm[c * NTAG + r];
            d_r[c - 1] = (unsigned char)r;
        }
    }
}

// ---------------- B3: path emission ----------------
__global__ void backtrack_emit(float* __restrict__ out) {
    __shared__ unsigned char b[CLEN * NTAG];
    int c = blockIdx.x, lane = threadIdx.x;
    const uint4* src = (const uint4*)(d_bps + c * CLEN * NTAG);
    uint4* dstv = (uint4*)b;
    for (int i = lane; i < (CLEN * NTAG) / 16; i += 32) dstv[i] = src[i];
    __syncwarp();
    if (lane == 0) {
        int x = d_r[c];
        float* o = out + 1 + c * CLEN;
        for (int t = CLEN - 1; t >= 0; t--) {
            o[t] = (float)x;
            x = b[t * NTAG + x];
        }
    }
}

// ---------------- launch ----------------
extern "C" void kernel_launch(void* const* d_in, const int* in_sizes, int n_in,
                              void* d_out, int out_size) {
    const float* x      = (const float*)d_in[0];
    const float* w_ih_f = (const float*)d_in[1];
    const float* b_ih_f = (const float*)d_in[3];
    const float* b_hh_f = (const float*)d_in[4];
    const float* w_ih_b = (const float*)d_in[5];
    const float* b_ih_b = (const float*)d_in[7];
    const float* b_hh_b = (const float*)d_in[8];
    const float* w_tag  = (const float*)d_in[9];
    const float* b_tag  = (const float*)d_in[10];
    const float* trans  = (const float*)d_in[11];
    float* out = (float*)d_out;

    cudaFuncSetAttribute(gemm_fused, cudaFuncAttributeMaxDynamicSharedMemorySize, GSMEM);
    cudaFuncSetAttribute(feats_kernel, cudaFuncAttributeMaxDynamicSharedMemorySize,
                         FT_TOK * HIDC * (int)sizeof(float));

    prep_kernel<<<XBLK + WBLK, 256>>>(x, w_ih_f, w_ih_b, b_ih_f, b_hh_f, b_ih_b, b_hh_b);

    dim3 ggrid(NPACK / 96, NTOK / 128);
    gemm_fused<<<ggrid, 256, GSMEM>>>();

    feats_kernel<<<NTOK / FT_TOK, 256, FT_TOK * HIDC * sizeof(float)>>>(w_tag, b_tag);

    viterbi_chunk_prod<<<NCHUNK, 512>>>(trans);
    viterbi_scan<<<1, 32>>>();
    viterbi_forward<<<NCHUNK, 32>>>(trans);
    terminal_and_scan<<<1, 32>>>(trans, out);
    backtrack_emit<<<NCHUNK, 32>>>(out);
}

// round 16
// speedup vs baseline: 1.0613x; 1.0613x over previous
#include <cuda_runtime.h>
#include <cuda_bf16.h>
#include <cstdint>

// ---------------- problem constants ----------------
#define NTOK   16384
#define HIN    768
#define NPACK  1536      // grouped gate cols: 16 groups x 96 (= i|g|o x 32 j)
#define HIDC   512
#define NTAG   20
#define NCHUNK 128
#define CLEN   128
#define NEGV   (-10000.0f)

// ---------------- device scratch ----------------
__device__ __nv_bfloat16 d_Ahi[(size_t)NTOK * HIN];
__device__ __nv_bfloat16 d_Alo[(size_t)NTOK * HIN];
__device__ __nv_bfloat16 d_Bhi[(size_t)NPACK * HIN];   // grouped rows, K-major
__device__ __nv_bfloat16 d_Blo[(size_t)NPACK * HIN];
__device__ float d_biasG[NPACK];
__device__ float d_enc[(size_t)NTOK * HIDC];
__device__ float d_feats[NTOK * NTAG];
__device__ float d_P[NCHUNK * NTAG * NTAG];
__device__ float d_fvs[NCHUNK * NTAG];
__device__ float d_finalfv[NTAG];
__device__ unsigned char d_bps[NTOK * NTAG];
__device__ unsigned char d_Wc[NCHUNK * NTAG];
__device__ unsigned char d_r[NCHUNK];

// ---------------- helpers ----------------
__device__ __forceinline__ uint32_t smem_u32(const void* p) {
    uint32_t a;
    asm("{ .reg .u64 t; cvta.to.shared.u64 t, %1; cvt.u32.u64 %0, t; }" : "=r"(a) : "l"(p));
    return a;
}
#define CP_ASYNC16(dst, src) \
    asm volatile("cp.async.cg.shared.global [%0], [%1], 16;" :: "r"(dst), "l"(src))
#define CP_COMMIT() asm volatile("cp.async.commit_group;" ::: "memory")
#define CP_WAIT(n)  asm volatile("cp.async.wait_group %0;" :: "n"(n) : "memory")

__device__ __forceinline__ void ldm_x4(uint32_t* r, uint32_t addr) {
    asm volatile("ldmatrix.sync.aligned.m8n8.x4.shared.b16 {%0,%1,%2,%3}, [%4];"
                 : "=r"(r[0]), "=r"(r[1]), "=r"(r[2]), "=r"(r[3]) : "r"(addr));
}
__device__ __forceinline__ void mma16816(float* c, const uint32_t* a, uint32_t b0, uint32_t b1) {
    asm volatile(
        "mma.sync.aligned.m16n8k16.row.col.f32.bf16.bf16.f32 "
        "{%0,%1,%2,%3}, {%4,%5,%6,%7}, {%8,%9}, {%0,%1,%2,%3};"
        : "+f"(c[0]), "+f"(c[1]), "+f"(c[2]), "+f"(c[3])
        : "r"(a[0]), "r"(a[1]), "r"(a[2]), "r"(a[3]), "r"(b0), "r"(b1));
}
__device__ __forceinline__ void split2(float f, __nv_bfloat16& h, __nv_bfloat16& l) {
    h = __float2bfloat16_rn(f);
    l = __float2bfloat16_rn(f - __bfloat162float(h));
}

// ---------------- K0: merged input split + weight pack ----------------
// grouped row n: g = n/96 (dir=g>>3, jblk=g&7), cg=n%96, gate=cg/32, jj=cg%32
#define XBLK ((NTOK * HIN / 4) / 256)     // 12288
#define WBLK ((NPACK * HIN / 4) / 256)    // 1152
__global__ void prep_kernel(const float* __restrict__ x,
                            const float* __restrict__ wf, const float* __restrict__ wb,
                            const float* __restrict__ bihf, const float* __restrict__ bhhf,
                            const float* __restrict__ bihb, const float* __restrict__ bhhb) {
    int b = blockIdx.x;
    if (b < XBLK) {
        int idx = b * 256 + threadIdx.x;
        float4 v = *(const float4*)(x + HIN + (size_t)idx * 4);  // skip token 0
        float f[4] = {v.x, v.y, v.z, v.w};
        __nv_bfloat16 hi[4], lo[4];
#pragma unroll
        for (int i = 0; i < 4; i++) split2(f[i], hi[i], lo[i]);
        *(ulonglong1*)(d_Ahi + (size_t)idx * 4) = *(ulonglong1*)hi;
        *(ulonglong1*)(d_Alo + (size_t)idx * 4) = *(ulonglong1*)lo;
    } else {
        int idx = (b - XBLK) * 256 + threadIdx.x;
        int n = idx / (HIN / 4);
        int kq = (idx % (HIN / 4)) * 4;
        int g = n / 96, cg = n % 96;
        int dir = g >> 3, jblk = g & 7;
        int gate = cg / 32, jj = cg % 32;
        int gateoff = (gate == 0) ? 0 : (gate == 1 ? 512 : 768);
        int r = gateoff + jblk * 32 + jj;
        const float* w = dir ? wb : wf;
        float4 v = *(const float4*)(w + (size_t)r * HIN + kq);
        float f[4] = {v.x, v.y, v.z, v.w};
        __nv_bfloat16 hi[4], lo[4];
#pragma unroll
        for (int i = 0; i < 4; i++) split2(f[i], hi[i], lo[i]);
        *(ulonglong1*)(d_Bhi + (size_t)n * HIN + kq) = *(ulonglong1*)hi;
        *(ulonglong1*)(d_Blo + (size_t)n * HIN + kq) = *(ulonglong1*)lo;
        if (kq == 0) {
            const float* bih = dir ? bihb : bihf;
            const float* bhh = dir ? bhhb : bhhf;
            d_biasG[n] = bih[r] + bhh[r];
        }
    }
}

// ---------------- K1: fused single-pass 3-product bf16 GEMM + LSTM activation ----------------
// CTA tile 128x96, 256 threads, 8 warps (warp tile 32x48), 2 CTAs/SM.
// Per 32-k stage: load Ahi,Alo (128x32 each) + Bhi,Blo (96x32 each) ONCE,
// issue AhiBhi + AhiBlo + AloBhi into the same f32 accumulators.
#define BKE 32
#define ASTR 40
#define NKI 24                    // 768/32
#define RA (128 * ASTR)           // one A region (elements)
#define RB (96 * ASTR)
#define SSTG (2 * RA + 2 * RB)    // 17920 elements = 35840 B per stage
#define OFF_AH 0
#define OFF_AL RA
#define OFF_BH (2 * RA)
#define OFF_BL (2 * RA + RB)
#define NST 3
#define GSMEM (NST * SSTG * 2)    // 107520 B
#define EXSTR 100

__global__ __launch_bounds__(256, 2) void gemm_fused() {
    extern __shared__ char dsm[];
    __nv_bfloat16* Ssm = (__nv_bfloat16*)dsm;
    float* Ex = (float*)dsm;                 // epilogue overlay: 64 x EXSTR fp32
    int tid = threadIdx.x;
    int wid = tid >> 5, lane = tid & 31;
    int wm = wid >> 1, wn = wid & 1;         // warp tile 32 x 48 (wm 0..3, wn 0..1)
    int g = blockIdx.x, bm = blockIdx.y;

    uint32_t sS = smem_u32(Ssm);
    const __nv_bfloat16* Agh = d_Ahi + (size_t)(bm * 128) * HIN;
    const __nv_bfloat16* Agl = d_Alo + (size_t)(bm * 128) * HIN;
    const __nv_bfloat16* Bgh = d_Bhi + (size_t)(g * 96) * HIN;
    const __nv_bfloat16* Bgl = d_Blo + (size_t)(g * 96) * HIN;

    float acc[2][6][4];
#pragma unroll
    for (int i = 0; i < 2; i++)
#pragma unroll
        for (int j = 0; j < 6; j++)
#pragma unroll
            for (int q = 0; q < 4; q++) acc[i][j][q] = 0.f;

#define LOAD_STAGE(s, kt)                                                                  \
    do {                                                                                   \
        uint32_t base_ = sS + (uint32_t)((s) * SSTG * 2);                                  \
        _Pragma("unroll")                                                                  \
        for (int i_ = 0; i_ < 2; i_++) {                                                   \
            int c_ = tid + i_ * 256;                                                       \
            int row_ = c_ >> 2, seg_ = c_ & 3;                                             \
            uint32_t so_ = (uint32_t)((row_ * ASTR + seg_ * 8) * 2);                       \
            size_t go_ = (size_t)row_ * HIN + (kt) * BKE + seg_ * 8;                       \
            CP_ASYNC16(base_ + OFF_AH * 2 + so_, Agh + go_);                               \
            CP_ASYNC16(base_ + OFF_AL * 2 + so_, Agl + go_);                               \
        }                                                                                  \
        _Pragma("unroll")                                                                  \
        for (int i_ = 0; i_ < 2; i_++) {                                                   \
            int c_ = tid + i_ * 256;                                                       \
            if (c_ < 384) {                                                                \
                int row_ = c_ >> 2, seg_ = c_ & 3;                                         \
                uint32_t so_ = (uint32_t)((row_ * ASTR + seg_ * 8) * 2);                   \
                size_t go_ = (size_t)row_ * HIN + (kt) * BKE + seg_ * 8;                   \
                CP_ASYNC16(base_ + OFF_BH * 2 + so_, Bgh + go_);                           \
                CP_ASYNC16(base_ + OFF_BL * 2 + so_, Bgl + go_);                           \
            }                                                                              \
        }                                                                                  \
    } while (0)

    LOAD_STAGE(0, 0); CP_COMMIT();
    LOAD_STAGE(1, 1); CP_COMMIT();

    for (int kt = 0; kt < NKI; kt++) {
        if (kt < NKI - 1) { CP_WAIT(1); }
        else { CP_WAIT(0); }
        __syncthreads();
        int cs = kt % NST;
        uint32_t sbase = sS + (uint32_t)(cs * SSTG * 2);

#pragma unroll
        for (int ks = 0; ks < 2; ks++) {
            int k0 = ks * 16;
            int arow = wm * 32 + (lane & 15);
            int hl = (lane >> 4) * 8;
            uint32_t afh[2][4], afl[2][4];
#pragma unroll
            for (int i = 0; i < 2; i++) {
                uint32_t ro = (uint32_t)(((arow + i * 16) * ASTR + k0 + hl) * 2);
                ldm_x4(afh[i], sbase + OFF_AH * 2 + ro);
                ldm_x4(afl[i], sbase + OFF_AL * 2 + ro);
            }
            uint32_t bfh[3][4], bfl[3][4];
#pragma unroll
            for (int p = 0; p < 3; p++) {
                int brow = wn * 48 + p * 16 + (lane & 15);
                uint32_t ro = (uint32_t)((brow * ASTR + k0 + hl) * 2);
                ldm_x4(bfh[p], sbase + OFF_BH * 2 + ro);
                ldm_x4(bfl[p], sbase + OFF_BL * 2 + ro);
            }
#pragma unroll
            for (int i = 0; i < 2; i++)
#pragma unroll
                for (int p = 0; p < 3; p++) {
                    mma16816(acc[i][2 * p + 0], afh[i], bfh[p][0], bfh[p][2]);
                    mma16816(acc[i][2 * p + 1], afh[i], bfh[p][1], bfh[p][3]);
                    mma16816(acc[i][2 * p + 0], afh[i], bfl[p][0], bfl[p][2]);
                    mma16816(acc[i][2 * p + 1], afh[i], bfl[p][1], bfl[p][3]);
                    mma16816(acc[i][2 * p + 0], afl[i], bfh[p][0], bfh[p][2]);
                    mma16816(acc[i][2 * p + 1], afl[i], bfh[p][1], bfh[p][3]);
                }
        }

        if (kt + 2 < NKI) {
            LOAD_STAGE((kt + 2) % NST, kt + 2);
            CP_COMMIT();
        }
    }
    __syncthreads();

    // ---- fused epilogue: bias + LSTM activation -> enc ----
    float2 bias[6];
#pragma unroll
    for (int jt = 0; jt < 6; jt++) {
        int col = g * 96 + wn * 48 + jt * 8 + (lane & 3) * 2;
        bias[jt] = *(const float2*)(d_biasG + col);
    }
    int dir = g >> 3, jblk = g & 7;
    int base = dir * 256 + jblk * 32;

#pragma unroll
    for (int ch = 0; ch < 2; ch++) {
        if ((wm >> 1) == ch) {
#pragma unroll
            for (int i = 0; i < 2; i++) {
                int r = (wm & 1) * 32 + i * 16 + (lane >> 2);
                int cbase = wn * 48 + (lane & 3) * 2;
#pragma unroll
                for (int jt = 0; jt < 6; jt++) {
                    int c = cbase + jt * 8;
                    Ex[r * EXSTR + c]           = acc[i][jt][0] + bias[jt].x;
                    Ex[r * EXSTR + c + 1]       = acc[i][jt][1] + bias[jt].y;
                    Ex[(r + 8) * EXSTR + c]     = acc[i][jt][2] + bias[jt].x;
                    Ex[(r + 8) * EXSTR + c + 1] = acc[i][jt][3] + bias[jt].y;
                }
            }
        }
        __syncthreads();
        // 64 rows x 32 j outputs = 2048 -> 8 iters of 256 threads
#pragma unroll
        for (int u = 0; u < 8; u++) {
            int idx = u * 256 + tid;
            int r = idx >> 5, j = idx & 31;
            float iv = Ex[r * EXSTR + j];
            float gv = Ex[r * EXSTR + 32 + j];
            float ov = Ex[r * EXSTR + 64 + j];
            float si = 1.f / (1.f + expf(-iv));
            float cc = si * tanhf(gv);
            float so = 1.f / (1.f + expf(-ov));
            d_enc[(size_t)(bm * 128 + ch * 64 + r) * HIDC + base + j] = so * tanhf(cc);
        }
        __syncthreads();
    }
}

// ---------------- K3: feats = enc @ w_tag^T + b_tag ----------------
#define FT_TOK 32
__global__ __launch_bounds__(256) void feats_kernel(const float* __restrict__ wtag,
                                                    const float* __restrict__ btag) {
    extern __shared__ float esm[];   // [FT_TOK][HIDC] = 64KB
    int warp = threadIdx.x >> 5, lane = threadIdx.x & 31;
    int tw = warp & 3, half = warp >> 2;
    float wreg[5][16];
#pragma unroll
    for (int t = 0; t < 5; t++)
#pragma unroll
        for (int q = 0; q < 16; q++)
            wreg[t][q] = wtag[(tw * 5 + t) * HIDC + q * 32 + lane];
    float bloc[5];
#pragma unroll
    for (int t = 0; t < 5; t++) bloc[t] = btag[tw * 5 + t];

    int tok0 = blockIdx.x * FT_TOK;
    const float4* src = (const float4*)(d_enc + (size_t)tok0 * HIDC);
    float4* dst = (float4*)esm;
    for (int i = threadIdx.x; i < FT_TOK * HIDC / 4; i += 256) dst[i] = src[i];
    __syncthreads();

    for (int tk = 0; tk < 8; tk++) {
        int tokA = half * 16 + tk;
        int tokB = tokA + 8;
        float sA[5] = {0.f, 0.f, 0.f, 0.f, 0.f};
        float sB[5] = {0.f, 0.f, 0.f, 0.f, 0.f};
#pragma unroll
        for (int q = 0; q < 16; q++) {
            float eA = esm[tokA * HIDC + q * 32 + lane];
            float eB = esm[tokB * HIDC + q * 32 + lane];
#pragma unroll
            for (int t = 0; t < 5; t++) {
                sA[t] += eA * wreg[t][q];
                sB[t] += eB * wreg[t][q];
            }
        }
#pragma unroll
        for (int t = 0; t < 5; t++) {
#pragma unroll
            for (int off = 16; off > 0; off >>= 1) {
                sA[t] += __shfl_xor_sync(0xffffffffu, sA[t], off);
                sB[t] += __shfl_xor_sync(0xffffffffu, sB[t], off);
            }
        }
        if (lane == 0) {
#pragma unroll
            for (int t = 0; t < 5; t++) {
                d_feats[(tok0 + tokA) * NTAG + tw * 5 + t] = sA[t] + bloc[t];
                d_feats[(tok0 + tokB) * NTAG + tw * 5 + t] = sB[t] + bloc[t];
            }
        }
    }
}

// ---------------- V1: per-chunk maxplus products (tree max) ----------------
__global__ __launch_bounds__(512) void viterbi_chunk_prod(const float* __restrict__ trans) {
    __shared__ float fsm[CLEN * NTAG];
    __shared__ float P[2][NTAG][NTAG];
    int c = blockIdx.x, tid = threadIdx.x;
    for (int i = tid; i < CLEN * NTAG; i += 512) fsm[i] = d_feats[c * CLEN * NTAG + i];
    __syncthreads();
    int j = tid / NTAG, k = tid % NTAG;
    bool act = (tid < NTAG * NTAG);
    float tr[NTAG];
    if (act) {
#pragma unroll
        for (int m = 0; m < NTAG; m++) tr[m] = trans[j * NTAG + m];
        P[0][j][k] = trans[j * NTAG + k] + fsm[j];
    }
    __syncthreads();
    int buf = 0;
    for (int t = 1; t < CLEN; t++) {
        if (act) {
            float v0 = -1e30f, v1 = -1e30f, v2 = -1e30f, v3 = -1e30f;
#pragma unroll
            for (int mm = 0; mm < 5; mm++) {
                v0 = fmaxf(v0, tr[4 * mm + 0] + P[buf][4 * mm + 0][k]);
                v1 = fmaxf(v1, tr[4 * mm + 1] + P[buf][4 * mm + 1][k]);
                v2 = fmaxf(v2, tr[4 * mm + 2] + P[buf][4 * mm + 2][k]);
                v3 = fmaxf(v3, tr[4 * mm + 3] + P[buf][4 * mm + 3][k]);
            }
            float v = fmaxf(fmaxf(v0, v1), fmaxf(v2, v3));
            P[buf ^ 1][j][k] = v + fsm[t * NTAG + j];
        }
        buf ^= 1;
        __syncthreads();
    }
    if (act) d_P[c * NTAG * NTAG + j * NTAG + k] = P[buf][j][k];
}

// ---------------- V2: sequential scan with prefetch (tree max) ----------------
__global__ void viterbi_scan() {
    __shared__ float Ps[NTAG * NTAG];
    __shared__ float fvsm[NTAG];
    int lane = threadIdx.x;
    float cur[13], nx[13];
#pragma unroll
    for (int t = 0; t < 13; t++) {
        int i = lane + 32 * t;
        cur[t] = (i < NTAG * NTAG) ? d_P[i] : 0.f;
    }
    float fv = (lane == 18) ? 0.f : NEGV;
    for (int c = 0; c < NCHUNK; c++) {
#pragma unroll
        for (int t = 0; t < 13; t++) {
            int i = lane + 32 * t;
            if (i < NTAG * NTAG) Ps[i] = cur[t];
        }
        if (lane < NTAG) { d_fvs[c * NTAG + lane] = fv; fvsm[lane] = fv; }
        __syncwarp();
        if (c + 1 < NCHUNK) {
#pragma unroll
            for (int t = 0; t < 13; t++) {
                int i = lane + 32 * t;
                nx[t] = (i < NTAG * NTAG) ? d_P[(c + 1) * NTAG * NTAG + i] : 0.f;
            }
        }
        if (lane < NTAG) {
            float v0 = -1e30f, v1 = -1e30f, v2 = -1e30f, v3 = -1e30f;
#pragma unroll
            for (int mm = 0; mm < 5; mm++) {
                v0 = fmaxf(v0, Ps[lane * NTAG + 4 * mm + 0] + fvsm[4 * mm + 0]);
                v1 = fmaxf(v1, Ps[lane * NTAG + 4 * mm + 1] + fvsm[4 * mm + 1]);
                v2 = fmaxf(v2, Ps[lane * NTAG + 4 * mm + 2] + fvsm[4 * mm + 2]);
                v3 = fmaxf(v3, Ps[lane * NTAG + 4 * mm + 3] + fvsm[4 * mm + 3]);
            }
            fv = fmaxf(fmaxf(v0, v1), fmaxf(v2, v3));
        }
        __syncwarp();
#pragma unroll
        for (int t = 0; t < 13; t++) cur[t] = nx[t];
    }
}

// ---------------- V3: per-chunk forward + backpointers + chunk table (merged) ----------------
__global__ void viterbi_forward(const float* __restrict__ trans) {
    __shared__ float fsm[CLEN * NTAG];
    __shared__ unsigned char bsm[CLEN * NTAG];
    int c = blockIdx.x, lane = threadIdx.x;
    for (int i = lane; i < CLEN * NTAG; i += 32) fsm[i] = d_feats[c * CLEN * NTAG + i];
    __syncwarp();
    bool act = lane < NTAG;
    float tr[NTAG];
    if (act) {
#pragma unroll
        for (int m = 0; m < NTAG; m++) tr[m] = trans[lane * NTAG + m];
    }
    float fv = act ? d_fvs[c * NTAG + lane] : -1e30f;
    for (int t = 0; t < CLEN; t++) {
        float best = -1e30f;
        int bi = 0;
#pragma unroll
        for (int k = 0; k < NTAG; k++) {
            float v = __shfl_sync(0xffffffffu, fv, k);
            if (act) {
                v += tr[k];
                if (v > best) { best = v; bi = k; }
            }
        }
        if (act) {
            bsm[t * NTAG + lane] = (unsigned char)bi;
            fv = best + fsm[t * NTAG + lane];
        }
    }
    if (c == NCHUNK - 1 && act) d_finalfv[lane] = fv;
    __syncwarp();
    uint4* dst = (uint4*)(d_bps + c * CLEN * NTAG);
    const uint4* srcv = (const uint4*)bsm;
    for (int i = lane; i < (CLEN * NTAG) / 16; i += 32) dst[i] = srcv[i];
    if (act) {
        int x = lane;
        for (int t = CLEN - 1; t >= 0; t--) x = bsm[t * NTAG + x];
        d_Wc[c * NTAG + lane] = (unsigned char)x;
    }
}

// ---------------- B2: terminal argmax + boundary scan ----------------
__global__ void terminal_and_scan(const float* __restrict__ trans, float* __restrict__ out) {
    __shared__ unsigned char Wsm[NCHUNK * NTAG];
    int lane = threadIdx.x;
    const uint4* src = (const uint4*)d_Wc;
    for (int i = lane; i < (NCHUNK * NTAG) / 16; i += 32) ((uint4*)Wsm)[i] = src[i];
    float term = (lane < NTAG) ? d_finalfv[lane] + trans[19 * NTAG + lane] : -1e30f;
    __syncwarp();
    float best = -1e30f;
    int bi = 0;
#pragma unroll
    for (int k = 0; k < NTAG; k++) {
        float v = __shfl_sync(0xffffffffu, term, k);
        if (v > best) { best = v; bi = k; }
    }
    if (lane == 0) {
        out[0] = best;
        int r = bi;
        d_r[NCHUNK - 1] = (unsigned char)r;
        for (int c = NCHUNK - 1; c >= 1; c--) {
            r = Wsm[c * NTAG + r];
            d_r[c - 1] = (unsigned char)r;
        }
    }
}

// ---------------- B3: path emission ----------------
__global__ void backtrack_emit(float* __restrict__ out) {
    __shared__ unsigned char b[CLEN * NTAG];
    int c = blockIdx.x, lane = threadIdx.x;
    const uint4* src = (const uint4*)(d_bps + c * CLEN * NTAG);
    uint4* dstv = (uint4*)b;
    for (int i = lane; i < (CLEN * NTAG) / 16; i += 32) dstv[i] = src[i];
    __syncwarp();
    if (lane == 0) {
        int x = d_r[c];
        float* o = out + 1 + c * CLEN;
        for (int t = CLEN - 1; t >= 0; t--) {
            o[t] = (float)x;
            x = b[t * NTAG + x];
        }
    }
}

// ---------------- launch ----------------
extern "C" void kernel_launch(void* const* d_in, const int* in_sizes, int n_in,
                              void* d_out, int out_size) {
    const float* x      = (const float*)d_in[0];
    const float* w_ih_f = (const float*)d_in[1];
    const float* b_ih_f = (const float*)d_in[3];
    const float* b_hh_f = (const float*)d_in[4];
    const float* w_ih_b = (const float*)d_in[5];
    const float* b_ih_b = (const float*)d_in[7];
    const float* b_hh_b = (const float*)d_in[8];
    const float* w_tag  = (const float*)d_in[9];
    const float* b_tag  = (const float*)d_in[10];
    const float* trans  = (const float*)d_in[11];
    float* out = (float*)d_out;

    cudaFuncSetAttribute(gemm_fused, cudaFuncAttributeMaxDynamicSharedMemorySize, GSMEM);
    cudaFuncSetAttribute(feats_kernel, cudaFuncAttributeMaxDynamicSharedMemorySize,
                         FT_TOK * HIDC * (int)sizeof(float));

    prep_kernel<<<XBLK + WBLK, 256>>>(x, w_ih_f, w_ih_b, b_ih_f, b_hh_f, b_ih_b, b_hh_b);

    dim3 ggrid(NPACK / 96, NTOK / 128);
    gemm_fused<<<ggrid, 256, GSMEM>>>();

    feats_kernel<<<NTOK / FT_TOK, 256, FT_TOK * HIDC * sizeof(float)>>>(w_tag, b_tag);

    viterbi_chunk_prod<<<NCHUNK, 512>>>(trans);
    viterbi_scan<<<1, 32>>>();
    viterbi_forward<<<NCHUNK, 32>>>(trans);
    terminal_and_scan<<<1, 32>>>(trans, out);
    backtrack_emit<<<NCHUNK, 32>>>(out);
}